// round 12
// baseline (speedup 1.0000x reference)
#include <cuda_runtime.h>
#include <cstdint>

#define T_STEPS 16
#define BATCH   32768
#define M_CTA   256
#define NBLK    (BATCH / M_CTA)     // 128 CTAs
#define NTHR    512                  // 16 warps
#define FLAG_CAP 8192
#define TAU     2e-4f

#define SM_CNT_OFF  131072u
#define SM_LIST_OFF 131088u
#define SMEM_BYTES  163872u

// int8 weight images (4-term fixed point), swizzled for ldmatrix:
// [L][ch][term*32768 + n*256 + ((q ^ (n&7))<<4 | (k&15))], q = k>>4
__device__ __align__(16) int8_t g_w23q[2][2][131072];
__device__ __align__(16) int8_t g_w4q[16384];   // [term*4096 + n*256 + pos], n=0..15
// spike bit planes: [buf][cta][t][wd(8)][row(256)]
__device__ uint32_t g_bits[2u * NBLK * T_STEPS * 8u * 256u];
#define GB(b,cta,t,wd,r) (((((b)*NBLK + (cta))*T_STEPS + (t))*8u + (wd))*256u + (r))

__global__ void prep_kernel(const float* __restrict__ w2, const float* __restrict__ w3,
                            const float* __restrict__ w4) {
    int idx = blockIdx.x * 256 + threadIdx.x;           // 0..131071
    {
        int L  = idx >> 16;
        int ch = (idx >> 15) & 1;
        int n  = (idx >> 8) & 127;
        int k  = idx & 255;
        float w  = (L ? w3 : w2)[(ch * 128 + n) * 256 + k];
        float q1 = rintf(w * 256.f);          float r = fmaf(q1, -0x1p-8f,  w);
        float q2 = rintf(r * 32768.f);              r = fmaf(q2, -0x1p-15f, r);
        float q3 = rintf(r * 4194304.f);            r = fmaf(q3, -0x1p-22f, r);
        float q4 = rintf(r * 536870912.f);
        int pos = n * 256 + ((((k >> 4) ^ (n & 7)) << 4) | (k & 15));
        g_w23q[L][ch][pos]         = (int8_t)(int)q1;
        g_w23q[L][ch][32768 + pos] = (int8_t)(int)q2;
        g_w23q[L][ch][65536 + pos] = (int8_t)(int)q3;
        g_w23q[L][ch][98304 + pos] = (int8_t)(int)q4;
    }
    if (idx < 4096) {
        int n = idx >> 8, k = idx & 255;
        float w  = w4[n * 256 + k];
        float q1 = rintf(w * 256.f);          float r = fmaf(q1, -0x1p-8f,  w);
        float q2 = rintf(r * 32768.f);              r = fmaf(q2, -0x1p-15f, r);
        float q3 = rintf(r * 4194304.f);            r = fmaf(q3, -0x1p-22f, r);
        float q4 = rintf(r * 536870912.f);
        int pos = n * 256 + ((((k >> 4) ^ (n & 7)) << 4) | (k & 15));
        g_w4q[pos]          = (int8_t)(int)q1;
        g_w4q[4096 + pos]   = (int8_t)(int)q2;
        g_w4q[8192 + pos]   = (int8_t)(int)q3;
        g_w4q[12288 + pos]  = (int8_t)(int)q4;
    }
}

__device__ __forceinline__ uint32_t smem_u32(const void* p) {
    uint32_t a;
    asm("{ .reg .u64 t; cvta.to.shared.u64 t, %1; cvt.u32.u64 %0, t; }" : "=r"(a) : "l"(p));
    return a;
}
__device__ __forceinline__ void ldsm4(uint32_t& r0, uint32_t& r1, uint32_t& r2, uint32_t& r3,
                                      uint32_t a) {
    asm volatile("ldmatrix.sync.aligned.m8n8.x4.shared.b16 {%0,%1,%2,%3}, [%4];"
                 : "=r"(r0), "=r"(r1), "=r"(r2), "=r"(r3) : "r"(a));
}
__device__ __forceinline__ void imma(int32_t& d0, int32_t& d1, int32_t& d2, int32_t& d3,
                                     uint32_t a0, uint32_t a1, uint32_t a2, uint32_t a3,
                                     uint32_t b0, uint32_t b1) {
    asm volatile("mma.sync.aligned.m16n8k32.row.col.s32.s8.s8.s32 "
                 "{%0,%1,%2,%3},{%4,%5,%6,%7},{%8,%9},{%0,%1,%2,%3};"
                 : "+r"(d0), "+r"(d1), "+r"(d2), "+r"(d3)
                 : "r"(a0), "r"(a1), "r"(a2), "r"(a3), "r"(b0), "r"(b1));
}
// 4 bits -> 4 s8 bytes of 0/1
__device__ __forceinline__ uint32_t exp8(uint32_t u) {
    return ((u & 0xFu) * 0x00204081u) & 0x01010101u;
}

extern __shared__ __align__(16) unsigned char smem[];

__global__ __launch_bounds__(NTHR, 1)
void snn_kernel(const float* __restrict__ x, const float* __restrict__ w1,
                const float* __restrict__ w2f, const float* __restrict__ w3f,
                float* __restrict__ out) {
    const int tid  = threadIdx.x;
    const int wid  = tid >> 5;
    const int lane = tid & 31;
    const int cta  = blockIdx.x;
    const int rb   = cta * M_CTA;
    const uint32_t swb = smem_u32(smem);

    const int g  = lane >> 2;          // row within fragment group
    const int cc = lane & 3;           // col/byte group
    const int nsub = ((lane >> 4) & 1) * 8 + (lane & 7);   // ldmatrix row select
    const int qbit = (lane >> 3) & 1;
    const int n7   = nsub & 7;
    const uint32_t rowb = (uint32_t)nsub * 256u;
    const int mrow = wid * 16;
    const float SC[4] = {0x1p-8f, 0x1p-15f, 0x1p-22f, 0x1p-29f};

    uint32_t* s_cnt  = (uint32_t*)(smem + SM_CNT_OFF);
    uint32_t* s_list = (uint32_t*)(smem + SM_LIST_OFF);

    // ===================== layer 1 (scalar fp32 IF, chain-exact) ============
    {
        float* sx  = (float*)smem;                 // [256][16]
        float* sw1 = (float*)(smem + 16384);       // [256][16]
        for (int i = tid; i < 256 * 16; i += NTHR) sx[i]  = x[rb * 16 + i];
        for (int i = tid; i < 256 * 16; i += NTHR) sw1[i] = w1[i];
        __syncthreads();
        int r = tid >> 1, h = tid & 1;
        float xr[16];
#pragma unroll
        for (int k = 0; k < 16; k++) xr[k] = sx[r * 16 + k];
        for (int g4 = 0; g4 < 4; g4++) {
            int wd = h * 4 + g4;
            uint32_t acc[T_STEPS];
#pragma unroll
            for (int t = 0; t < T_STEPS; t++) acc[t] = 0;
            for (int b = 0; b < 32; b++) {
                int o = wd * 32 + b;
                float a = 0.f;
#pragma unroll
                for (int k = 0; k < 16; k++) a = fmaf(xr[k], sw1[o * 16 + k], a);
                float v = 0.f;
#pragma unroll
                for (int t = 0; t < T_STEPS; t++) {
                    v += a;
                    if (v >= 1.f) { v -= 1.f; acc[t] |= (1u << b); }
                }
            }
#pragma unroll
            for (int t = 0; t < T_STEPS; t++) g_bits[GB(0, cta, t, wd, r)] = acc[t];
        }
    }

    // ============ layers 2 & 3: exact s8 IMMA + margin fix-up ===============
    for (int L = 0; L < 2; L++) {
        const int sb = L, db = 1 - L;
        if (tid == 0) *s_cnt = 0;
        for (int ch = 0; ch < 2; ch++) {
            __syncthreads();
            { // stage 4-term weight chunk (128KB)
                const uint4* src = (const uint4*)&g_w23q[L][ch][0];
                uint4* dst = (uint4*)smem;
                for (int i = tid; i < 8192; i += NTHR) dst[i] = src[i];
            }
            __syncthreads();

            for (int ng = 0; ng < 2; ng++) {
                float v[8][4];
#pragma unroll
                for (int nt = 0; nt < 8; nt++)
#pragma unroll
                    for (int j = 0; j < 4; j++) v[nt][j] = 0.f;
                uint32_t fl = 0;

                for (int t = 0; t < T_STEPS; t++) {
                    uint32_t A0[8], A1[8], A2[8], A3[8];
#pragma unroll
                    for (int kt = 0; kt < 8; kt++) {
                        uint32_t w0 = g_bits[GB(sb, cta, t, kt, mrow + g)];
                        uint32_t w1b = g_bits[GB(sb, cta, t, kt, mrow + 8 + g)];
                        A0[kt] = exp8(w0 >> (4 * cc));
                        A1[kt] = exp8(w1b >> (4 * cc));
                        A2[kt] = exp8(w0 >> (16 + 4 * cc));
                        A3[kt] = exp8(w1b >> (16 + 4 * cc));
                    }
#pragma unroll
                    for (int np = 0; np < 4; np++) {
                        float a[8];
#pragma unroll
                        for (int j = 0; j < 8; j++) a[j] = 0.f;
#pragma unroll
                        for (int term = 0; term < 4; term++) {
                            int32_t d[8];
#pragma unroll
                            for (int j = 0; j < 8; j++) d[j] = 0;
                            const uint32_t base = swb + (uint32_t)((ng * 4 + np) * 16) * 256u
                                                + (uint32_t)term * 32768u + rowb;
#pragma unroll
                            for (int kt = 0; kt < 8; kt++) {
                                uint32_t f0, f1, f2, f3;
                                ldsm4(f0, f1, f2, f3,
                                      base + (uint32_t)((((kt << 1) + qbit) ^ n7) << 4));
                                imma(d[0], d[1], d[2], d[3],
                                     A0[kt], A1[kt], A2[kt], A3[kt], f0, f1);
                                imma(d[4], d[5], d[6], d[7],
                                     A0[kt], A1[kt], A2[kt], A3[kt], f2, f3);
                            }
#pragma unroll
                            for (int j = 0; j < 8; j++)
                                a[j] = fmaf(SC[term], __int2float_rn(d[j]), a[j]);
                        }
#pragma unroll
                        for (int j = 0; j < 4; j++) v[2 * np][j]     += a[j];
#pragma unroll
                        for (int j = 0; j < 4; j++) v[2 * np + 1][j] += a[4 + j];
                    }

                    // IF epilogue: margin flag, spike, soft reset, publish bits
#pragma unroll
                    for (int lw = 0; lw < 2; lw++) {
                        uint32_t m0 = 0, m1 = 0;
#pragma unroll
                        for (int j2 = 0; j2 < 4; j2++) {
                            const int nt = lw * 4 + j2;
                            const int bp = (j2 << 3) + (cc << 1);
                            if (fabsf(v[nt][0] - 1.f) < TAU) fl |= 1u << (nt * 4 + 0);
                            if (fabsf(v[nt][1] - 1.f) < TAU) fl |= 1u << (nt * 4 + 1);
                            if (fabsf(v[nt][2] - 1.f) < TAU) fl |= 1u << (nt * 4 + 2);
                            if (fabsf(v[nt][3] - 1.f) < TAU) fl |= 1u << (nt * 4 + 3);
                            if (v[nt][0] >= 1.f) { v[nt][0] -= 1.f; m0 |= 1u << bp; }
                            if (v[nt][1] >= 1.f) { v[nt][1] -= 1.f; m0 |= 2u << bp; }
                            if (v[nt][2] >= 1.f) { v[nt][2] -= 1.f; m1 |= 1u << bp; }
                            if (v[nt][3] >= 1.f) { v[nt][3] -= 1.f; m1 |= 2u << bp; }
                        }
                        m0 |= __shfl_xor_sync(0xffffffffu, m0, 1);
                        m0 |= __shfl_xor_sync(0xffffffffu, m0, 2);
                        m1 |= __shfl_xor_sync(0xffffffffu, m1, 1);
                        m1 |= __shfl_xor_sync(0xffffffffu, m1, 2);
                        if (cc == 0) {
                            const int wd = ch * 4 + ng * 2 + lw;
                            g_bits[GB(db, cta, t, wd, mrow + g)]     = m0;
                            g_bits[GB(db, cta, t, wd, mrow + 8 + g)] = m1;
                        }
                    }
                }

                // append flagged neurons (row, o) to fix-up list
                while (fl) {
                    const int bit = __ffs(fl) - 1;
                    fl &= fl - 1;
                    const int nt = bit >> 2, j = bit & 3;
                    const int row = mrow + g + ((j >> 1) << 3);
                    const int o   = ch * 128 + ng * 64 + nt * 8 + 2 * cc + (j & 1);
                    uint32_t pos = atomicAdd(s_cnt, 1u);
                    if (pos < FLAG_CAP)
                        s_list[pos] = ((uint32_t)o << 8) | (uint32_t)row;
                }
            }
        }

        // -------- fix-up: chain-exact recompute of flagged neurons ----------
        __syncthreads();
        {
            int cnt = (int)*s_cnt;
            if (cnt > FLAG_CAP) cnt = FLAG_CAP;
            const float* wsrc = L ? w3f : w2f;
            for (int ii = tid; ii < cnt; ii += NTHR) {
                const uint32_t e = s_list[ii];
                const int row = (int)(e & 255u);
                const int o   = (int)((e >> 8) & 255u);
                const float* wrow = wsrc + o * 256;
                float vm = 0.f;
                for (int t = 0; t < T_STEPS; t++) {
                    float a = 0.f;
                    for (int w8 = 0; w8 < 8; w8++) {
                        uint32_t bits = g_bits[GB(sb, cta, t, w8, row)];
                        while (bits) {
                            const int b = __ffs(bits) - 1;
                            bits &= bits - 1;
                            a += wrow[w8 * 32 + b];   // == fmaf(w,1,a), chain-exact
                        }
                    }
                    vm += a;
                    uint32_t s = 0;
                    if (vm >= 1.f) { vm -= 1.f; s = 1u; }
                    uint32_t* wp = &g_bits[GB(db, cta, t, o >> 5, row)];
                    const uint32_t cur = (*wp >> (o & 31)) & 1u;
                    if (cur != s) atomicXor(wp, 1u << (o & 31));
                }
            }
        }
        __syncthreads();
    }

    // ===================== layer 4 (one warp per t, exact s8) ===============
    {
        const uint4* src = (const uint4*)g_w4q;
        uint4* dst = (uint4*)smem;
        for (int i = tid; i < 1024; i += NTHR) dst[i] = src[i];
    }
    __syncthreads();
    {
        const int t = wid;
        for (int rt = 0; rt < 16; rt++) {
            uint32_t A0[8], A1[8], A2[8], A3[8];
#pragma unroll
            for (int kt = 0; kt < 8; kt++) {
                uint32_t w0 = g_bits[GB(0, cta, t, kt, rt * 16 + g)];
                uint32_t w1b = g_bits[GB(0, cta, t, kt, rt * 16 + 8 + g)];
                A0[kt] = exp8(w0 >> (4 * cc));
                A1[kt] = exp8(w1b >> (4 * cc));
                A2[kt] = exp8(w0 >> (16 + 4 * cc));
                A3[kt] = exp8(w1b >> (16 + 4 * cc));
            }
            float o0[4], o1[4];
#pragma unroll
            for (int j = 0; j < 4; j++) { o0[j] = 0.f; o1[j] = 0.f; }
#pragma unroll
            for (int term = 0; term < 4; term++) {
                int32_t d[8];
#pragma unroll
                for (int j = 0; j < 8; j++) d[j] = 0;
                const uint32_t base = swb + (uint32_t)term * 4096u + rowb;
#pragma unroll
                for (int kt = 0; kt < 8; kt++) {
                    uint32_t f0, f1, f2, f3;
                    ldsm4(f0, f1, f2, f3,
                          base + (uint32_t)((((kt << 1) + qbit) ^ n7) << 4));
                    imma(d[0], d[1], d[2], d[3], A0[kt], A1[kt], A2[kt], A3[kt], f0, f1);
                    imma(d[4], d[5], d[6], d[7], A0[kt], A1[kt], A2[kt], A3[kt], f2, f3);
                }
#pragma unroll
                for (int j = 0; j < 4; j++) {
                    o0[j] = fmaf(SC[term], __int2float_rn(d[j]),     o0[j]);
                    o1[j] = fmaf(SC[term], __int2float_rn(d[4 + j]), o1[j]);
                }
            }
            const size_t row0 = (size_t)t * BATCH + rb + rt * 16;
            *(float2*)(out + (row0 + g)     * 16 + 2 * cc)     = make_float2(o0[0], o0[1]);
            *(float2*)(out + (row0 + g)     * 16 + 8 + 2 * cc) = make_float2(o1[0], o1[1]);
            *(float2*)(out + (row0 + 8 + g) * 16 + 2 * cc)     = make_float2(o0[2], o0[3]);
            *(float2*)(out + (row0 + 8 + g) * 16 + 8 + 2 * cc) = make_float2(o1[2], o1[3]);
        }
    }
}

extern "C" void kernel_launch(void* const* d_in, const int* in_sizes, int n_in,
                              void* d_out, int out_size) {
    const float* x  = (const float*)d_in[0];
    const float* w1 = (const float*)d_in[1];
    const float* w2 = (const float*)d_in[2];
    const float* w3 = (const float*)d_in[3];
    const float* w4 = (const float*)d_in[4];
    float* out = (float*)d_out;

    cudaFuncSetAttribute(snn_kernel, cudaFuncAttributeMaxDynamicSharedMemorySize,
                         SMEM_BYTES);
    prep_kernel<<<512, 256>>>(w2, w3, w4);
    snn_kernel<<<NBLK, NTHR, SMEM_BYTES>>>(x, w1, w2, w3, out);
}

// round 13
// speedup vs baseline: 1.2901x; 1.2901x over previous
#include <cuda_runtime.h>
#include <cstdint>

#define T_STEPS 16
#define BATCH   32768
#define M_CTA   256
#define NBLK    (BATCH / M_CTA)     // 128 CTAs
#define NTHR    512                  // 16 warps
#define FLAG_CAP 12288
#define TAU     4e-3f

#define SM_CNT_OFF  65536u
#define SM_LIST_OFF 65552u
#define SMEM_BYTES  (65552u + 4u * FLAG_CAP + 16u)

// int8 weight images (2-term fixed point: scales 2^-8, 2^-16), ldmatrix-swizzled:
// [L][ch][term*32768 + n*256 + ((q ^ (n&7))<<4 | (k&15))], q = k>>4
__device__ __align__(16) int8_t g_w23q[2][2][65536];
__device__ __align__(16) int8_t g_w4q[8192];   // [term*4096 + n*256 + pos], n=0..15
// spike bit planes: [buf][cta][t][wd(8)][row(256)]
__device__ uint32_t g_bits[2u * NBLK * T_STEPS * 8u * 256u];
#define GB(b,cta,t,wd,r) (((((b)*NBLK + (cta))*T_STEPS + (t))*8u + (wd))*256u + (r))

__global__ void prep_kernel(const float* __restrict__ w2, const float* __restrict__ w3,
                            const float* __restrict__ w4) {
    int idx = blockIdx.x * 256 + threadIdx.x;           // 0..131071
    {
        int L  = idx >> 16;
        int ch = (idx >> 15) & 1;
        int n  = (idx >> 8) & 127;
        int k  = idx & 255;
        float w  = (L ? w3 : w2)[(ch * 128 + n) * 256 + k];
        float q1 = rintf(w * 256.f);
        float r  = fmaf(q1, -0x1p-8f, w);
        float q2 = fminf(fmaxf(rintf(r * 65536.f), -127.f), 127.f);
        int pos = n * 256 + ((((k >> 4) ^ (n & 7)) << 4) | (k & 15));
        g_w23q[L][ch][pos]         = (int8_t)(int)q1;
        g_w23q[L][ch][32768 + pos] = (int8_t)(int)q2;
    }
    if (idx < 4096) {
        int n = idx >> 8, k = idx & 255;
        float w  = w4[n * 256 + k];
        float q1 = rintf(w * 256.f);
        float r  = fmaf(q1, -0x1p-8f, w);
        float q2 = fminf(fmaxf(rintf(r * 65536.f), -127.f), 127.f);
        int pos = n * 256 + ((((k >> 4) ^ (n & 7)) << 4) | (k & 15));
        g_w4q[pos]        = (int8_t)(int)q1;
        g_w4q[4096 + pos] = (int8_t)(int)q2;
    }
}

__device__ __forceinline__ uint32_t smem_u32(const void* p) {
    uint32_t a;
    asm("{ .reg .u64 t; cvta.to.shared.u64 t, %1; cvt.u32.u64 %0, t; }" : "=r"(a) : "l"(p));
    return a;
}
__device__ __forceinline__ void ldsm4(uint32_t& r0, uint32_t& r1, uint32_t& r2, uint32_t& r3,
                                      uint32_t a) {
    asm volatile("ldmatrix.sync.aligned.m8n8.x4.shared.b16 {%0,%1,%2,%3}, [%4];"
                 : "=r"(r0), "=r"(r1), "=r"(r2), "=r"(r3) : "r"(a));
}
__device__ __forceinline__ void imma(int32_t& d0, int32_t& d1, int32_t& d2, int32_t& d3,
                                     uint32_t a0, uint32_t a1, uint32_t a2, uint32_t a3,
                                     uint32_t b0, uint32_t b1) {
    asm volatile("mma.sync.aligned.m16n8k32.row.col.s32.s8.s8.s32 "
                 "{%0,%1,%2,%3},{%4,%5,%6,%7},{%8,%9},{%0,%1,%2,%3};"
                 : "+r"(d0), "+r"(d1), "+r"(d2), "+r"(d3)
                 : "r"(a0), "r"(a1), "r"(a2), "r"(a3), "r"(b0), "r"(b1));
}
// 4 bits -> 4 s8 bytes of 0/1
__device__ __forceinline__ uint32_t exp8(uint32_t u) {
    return ((u & 0xFu) * 0x00204081u) & 0x01010101u;
}

extern __shared__ __align__(16) unsigned char smem[];

__global__ __launch_bounds__(NTHR, 1)
void snn_kernel(const float* __restrict__ x, const float* __restrict__ w1,
                const float* __restrict__ w2f, const float* __restrict__ w3f,
                float* __restrict__ out) {
    const int tid  = threadIdx.x;
    const int wid  = tid >> 5;
    const int lane = tid & 31;
    const int cta  = blockIdx.x;
    const int rb   = cta * M_CTA;
    const uint32_t swb = smem_u32(smem);

    const int g  = lane >> 2;          // row within fragment group
    const int cc = lane & 3;           // col/byte group
    const int nsub = ((lane >> 4) & 1) * 8 + (lane & 7);   // ldmatrix row select
    const int qbit = (lane >> 3) & 1;
    const int n7   = nsub & 7;
    const uint32_t rowb = (uint32_t)nsub * 256u;
    const int mrow = wid * 16;
    const float SC[2] = {0x1p-8f, 0x1p-16f};

    uint32_t* s_cnt  = (uint32_t*)(smem + SM_CNT_OFF);
    uint32_t* s_list = (uint32_t*)(smem + SM_LIST_OFF);

    // ===================== layer 1 (scalar fp32 IF, chain-exact) ============
    {
        float* sx  = (float*)smem;                 // [256][16]
        float* sw1 = (float*)(smem + 16384);       // [256][16]
        for (int i = tid; i < 256 * 16; i += NTHR) sx[i]  = x[rb * 16 + i];
        for (int i = tid; i < 256 * 16; i += NTHR) sw1[i] = w1[i];
        __syncthreads();
        int r = tid >> 1, h = tid & 1;
        float xr[16];
#pragma unroll
        for (int k = 0; k < 16; k++) xr[k] = sx[r * 16 + k];
        for (int g4 = 0; g4 < 4; g4++) {
            int wd = h * 4 + g4;
            uint32_t acc[T_STEPS];
#pragma unroll
            for (int t = 0; t < T_STEPS; t++) acc[t] = 0;
            for (int b = 0; b < 32; b++) {
                int o = wd * 32 + b;
                float a = 0.f;
#pragma unroll
                for (int k = 0; k < 16; k++) a = fmaf(xr[k], sw1[o * 16 + k], a);
                float v = 0.f;
#pragma unroll
                for (int t = 0; t < T_STEPS; t++) {
                    v += a;
                    if (v >= 1.f) { v -= 1.f; acc[t] |= (1u << b); }
                }
            }
#pragma unroll
            for (int t = 0; t < T_STEPS; t++) g_bits[GB(0, cta, t, wd, r)] = acc[t];
        }
    }

    // ============ layers 2 & 3: 2-term s8 IMMA + margin fix-up ==============
    for (int L = 0; L < 2; L++) {
        const int sb = L, db = 1 - L;
        if (tid == 0) *s_cnt = 0;
        for (int ch = 0; ch < 2; ch++) {
            __syncthreads();
            { // stage 2-term weight chunk (64KB)
                const uint4* src = (const uint4*)&g_w23q[L][ch][0];
                uint4* dst = (uint4*)smem;
                for (int i = tid; i < 4096; i += NTHR) dst[i] = src[i];
            }
            __syncthreads();

            for (int ng = 0; ng < 2; ng++) {
                float v[8][4];
#pragma unroll
                for (int nt = 0; nt < 8; nt++)
#pragma unroll
                    for (int j = 0; j < 4; j++) v[nt][j] = 0.f;
                uint32_t fl = 0;

                for (int t = 0; t < T_STEPS; t++) {
                    uint32_t A0[8], A1[8], A2[8], A3[8];
#pragma unroll
                    for (int kt = 0; kt < 8; kt++) {
                        uint32_t w0 = g_bits[GB(sb, cta, t, kt, mrow + g)];
                        uint32_t w1b = g_bits[GB(sb, cta, t, kt, mrow + 8 + g)];
                        A0[kt] = exp8(w0 >> (4 * cc));
                        A1[kt] = exp8(w1b >> (4 * cc));
                        A2[kt] = exp8(w0 >> (16 + 4 * cc));
                        A3[kt] = exp8(w1b >> (16 + 4 * cc));
                    }
#pragma unroll
                    for (int np = 0; np < 4; np++) {
                        float a[8];
#pragma unroll
                        for (int j = 0; j < 8; j++) a[j] = 0.f;
#pragma unroll
                        for (int term = 0; term < 2; term++) {
                            int32_t d[8];
#pragma unroll
                            for (int j = 0; j < 8; j++) d[j] = 0;
                            const uint32_t base = swb + (uint32_t)((ng * 4 + np) * 16) * 256u
                                                + (uint32_t)term * 32768u + rowb;
#pragma unroll
                            for (int kt = 0; kt < 8; kt++) {
                                uint32_t f0, f1, f2, f3;
                                ldsm4(f0, f1, f2, f3,
                                      base + (uint32_t)((((kt << 1) + qbit) ^ n7) << 4));
                                imma(d[0], d[1], d[2], d[3],
                                     A0[kt], A1[kt], A2[kt], A3[kt], f0, f1);
                                imma(d[4], d[5], d[6], d[7],
                                     A0[kt], A1[kt], A2[kt], A3[kt], f2, f3);
                            }
#pragma unroll
                            for (int j = 0; j < 8; j++)
                                a[j] = fmaf(SC[term], __int2float_rn(d[j]), a[j]);
                        }
#pragma unroll
                        for (int j = 0; j < 4; j++) v[2 * np][j]     += a[j];
#pragma unroll
                        for (int j = 0; j < 4; j++) v[2 * np + 1][j] += a[4 + j];
                    }

                    // IF epilogue: margin flag, spike, soft reset, publish bits
#pragma unroll
                    for (int lw = 0; lw < 2; lw++) {
                        uint32_t m0 = 0, m1 = 0;
#pragma unroll
                        for (int j2 = 0; j2 < 4; j2++) {
                            const int nt = lw * 4 + j2;
                            const int bp = (j2 << 3) + (cc << 1);
                            if (fabsf(v[nt][0] - 1.f) < TAU) fl |= 1u << (nt * 4 + 0);
                            if (fabsf(v[nt][1] - 1.f) < TAU) fl |= 1u << (nt * 4 + 1);
                            if (fabsf(v[nt][2] - 1.f) < TAU) fl |= 1u << (nt * 4 + 2);
                            if (fabsf(v[nt][3] - 1.f) < TAU) fl |= 1u << (nt * 4 + 3);
                            if (v[nt][0] >= 1.f) { v[nt][0] -= 1.f; m0 |= 1u << bp; }
                            if (v[nt][1] >= 1.f) { v[nt][1] -= 1.f; m0 |= 2u << bp; }
                            if (v[nt][2] >= 1.f) { v[nt][2] -= 1.f; m1 |= 1u << bp; }
                            if (v[nt][3] >= 1.f) { v[nt][3] -= 1.f; m1 |= 2u << bp; }
                        }
                        m0 |= __shfl_xor_sync(0xffffffffu, m0, 1);
                        m0 |= __shfl_xor_sync(0xffffffffu, m0, 2);
                        m1 |= __shfl_xor_sync(0xffffffffu, m1, 1);
                        m1 |= __shfl_xor_sync(0xffffffffu, m1, 2);
                        if (cc == 0) {
                            const int wd = ch * 4 + ng * 2 + lw;
                            g_bits[GB(db, cta, t, wd, mrow + g)]     = m0;
                            g_bits[GB(db, cta, t, wd, mrow + 8 + g)] = m1;
                        }
                    }
                }

                // append flagged neurons (row, o) to fix-up list
                while (fl) {
                    const int bit = __ffs(fl) - 1;
                    fl &= fl - 1;
                    const int nt = bit >> 2, j = bit & 3;
                    const int row = mrow + g + ((j >> 1) << 3);
                    const int o   = ch * 128 + ng * 64 + nt * 8 + 2 * cc + (j & 1);
                    uint32_t pos = atomicAdd(s_cnt, 1u);
                    if (pos < FLAG_CAP)
                        s_list[pos] = ((uint32_t)o << 8) | (uint32_t)row;
                }
            }
        }

        // -------- fix-up: chain-exact recompute of flagged neurons ----------
        __syncthreads();
        {
            int cnt = (int)*s_cnt;
            if (cnt > FLAG_CAP) cnt = FLAG_CAP;
            const float* wsrc = L ? w3f : w2f;
            for (int ii = tid; ii < cnt; ii += NTHR) {
                const uint32_t e = s_list[ii];
                const int row = (int)(e & 255u);
                const int o   = (int)((e >> 8) & 255u);
                const float* wrow = wsrc + o * 256;
                float vm = 0.f;
                for (int t = 0; t < T_STEPS; t++) {
                    float a = 0.f;
                    for (int w8 = 0; w8 < 8; w8++) {
                        uint32_t bits = g_bits[GB(sb, cta, t, w8, row)];
                        while (bits) {
                            const int b = __ffs(bits) - 1;
                            bits &= bits - 1;
                            a += wrow[w8 * 32 + b];   // == fmaf(w,1,a), chain-exact
                        }
                    }
                    vm += a;
                    uint32_t s = 0;
                    if (vm >= 1.f) { vm -= 1.f; s = 1u; }
                    uint32_t* wp = &g_bits[GB(db, cta, t, o >> 5, row)];
                    const uint32_t cur = (*wp >> (o & 31)) & 1u;
                    if (cur != s) atomicXor(wp, 1u << (o & 31));
                }
            }
        }
        __syncthreads();
    }

    // ===================== layer 4 (one warp per t, 2-term s8) ==============
    {
        const uint4* src = (const uint4*)g_w4q;
        uint4* dst = (uint4*)smem;
        for (int i = tid; i < 512; i += NTHR) dst[i] = src[i];
    }
    __syncthreads();
    {
        const int t = wid;
        for (int rt = 0; rt < 16; rt++) {
            uint32_t A0[8], A1[8], A2[8], A3[8];
#pragma unroll
            for (int kt = 0; kt < 8; kt++) {
                uint32_t w0 = g_bits[GB(0, cta, t, kt, rt * 16 + g)];
                uint32_t w1b = g_bits[GB(0, cta, t, kt, rt * 16 + 8 + g)];
                A0[kt] = exp8(w0 >> (4 * cc));
                A1[kt] = exp8(w1b >> (4 * cc));
                A2[kt] = exp8(w0 >> (16 + 4 * cc));
                A3[kt] = exp8(w1b >> (16 + 4 * cc));
            }
            float o0[4], o1[4];
#pragma unroll
            for (int j = 0; j < 4; j++) { o0[j] = 0.f; o1[j] = 0.f; }
#pragma unroll
            for (int term = 0; term < 2; term++) {
                int32_t d[8];
#pragma unroll
                for (int j = 0; j < 8; j++) d[j] = 0;
                const uint32_t base = swb + (uint32_t)term * 4096u + rowb;
#pragma unroll
                for (int kt = 0; kt < 8; kt++) {
                    uint32_t f0, f1, f2, f3;
                    ldsm4(f0, f1, f2, f3,
                          base + (uint32_t)((((kt << 1) + qbit) ^ n7) << 4));
                    imma(d[0], d[1], d[2], d[3], A0[kt], A1[kt], A2[kt], A3[kt], f0, f1);
                    imma(d[4], d[5], d[6], d[7], A0[kt], A1[kt], A2[kt], A3[kt], f2, f3);
                }
#pragma unroll
                for (int j = 0; j < 4; j++) {
                    o0[j] = fmaf(SC[term], __int2float_rn(d[j]),     o0[j]);
                    o1[j] = fmaf(SC[term], __int2float_rn(d[4 + j]), o1[j]);
                }
            }
            const size_t row0 = (size_t)t * BATCH + rb + rt * 16;
            *(float2*)(out + (row0 + g)     * 16 + 2 * cc)     = make_float2(o0[0], o0[1]);
            *(float2*)(out + (row0 + g)     * 16 + 8 + 2 * cc) = make_float2(o1[0], o1[1]);
            *(float2*)(out + (row0 + 8 + g) * 16 + 2 * cc)     = make_float2(o0[2], o0[3]);
            *(float2*)(out + (row0 + 8 + g) * 16 + 8 + 2 * cc) = make_float2(o1[2], o1[3]);
        }
    }
}

extern "C" void kernel_launch(void* const* d_in, const int* in_sizes, int n_in,
                              void* d_out, int out_size) {
    const float* x  = (const float*)d_in[0];
    const float* w1 = (const float*)d_in[1];
    const float* w2 = (const float*)d_in[2];
    const float* w3 = (const float*)d_in[3];
    const float* w4 = (const float*)d_in[4];
    float* out = (float*)d_out;

    cudaFuncSetAttribute(snn_kernel, cudaFuncAttributeMaxDynamicSharedMemorySize,
                         SMEM_BYTES);
    prep_kernel<<<512, 256>>>(w2, w3, w4);
    snn_kernel<<<NBLK, NTHR, SMEM_BYTES>>>(x, w1, w2, w3, out);
}